// round 1
// baseline (speedup 1.0000x reference)
#include <cuda_runtime.h>

#define D    128
#define TM   64
#define XSS  132          // padded row stride for Xs/Ts to dodge bank conflicts
#define NMAX 50000

// Scratch (static device globals — no allocation in kernel_launch)
__device__ float g_y[NMAX * D];     // per-node MLP1 output
__device__ float g_sum[NMAX * D];   // scatter-add accumulator
__device__ float g_cnt[NMAX];       // in-degree

__global__ void zero_kernel(int n4, int n) {
    int i = blockIdx.x * blockDim.x + threadIdx.x;
    if (i < n4) ((float4*)g_sum)[i] = make_float4(0.f, 0.f, 0.f, 0.f);
    if (i < n)  g_cnt[i] = 0.f;
}

// One warp per edge: gather y[col] (128 floats), atomicAdd float4 into sum[row]
__global__ void scatter_kernel(const int* __restrict__ ei, int E) {
    int g = blockIdx.x * blockDim.x + threadIdx.x;
    int e = g >> 5;
    if (e >= E) return;
    int lane = g & 31;
    int dst = ei[e];        // row (destination)
    int src = ei[E + e];    // col (source)
    float4 v = ((const float4*)g_y)[src * 32 + lane];
    atomicAdd(((float4*)g_sum) + dst * 32 + lane, v);
    if (lane == 0) atomicAdd(&g_cnt[dst], 1.0f);
}

// mode 0:  y = MLP1(logmap0(x))           (reads x, writes g_y)
// mode 1:  out = expmap0(MLP2(sum/cnt))   (reads g_sum/g_cnt, writes out)
__global__ __launch_bounds__(256, 1) void fused_mlp_kernel(
    const float* __restrict__ in,
    const float* __restrict__ W1, const float* __restrict__ B1,
    const float* __restrict__ W2, const float* __restrict__ B2,
    float* __restrict__ out, int N, int mode)
{
    extern __shared__ float sm[];
    float* Xs = sm;                  // TM * XSS
    float* Ts = Xs + TM * XSS;       // TM * XSS
    float* Ws = Ts + TM * XSS;       // D * D
    const int tid  = threadIdx.x;
    const int tx   = tid & 15;       // 16 col-groups of 8
    const int ty   = tid >> 4;       // 16 row-groups of 4
    const int row0 = blockIdx.x * TM;

    // ---- load input tile (zero-fill OOB rows) ----
    #pragma unroll
    for (int s = 0; s < 8; ++s) {
        int e  = tid + s * 256;        // 0..2047 float4 slots
        int r  = e >> 5, c4 = e & 31;
        int rg = row0 + r;
        float4 v = make_float4(0.f, 0.f, 0.f, 0.f);
        if (rg < N) {
            if (mode == 0) {
                v = ((const float4*)in)[rg * 32 + c4];
            } else {
                float inv = 1.0f / (g_cnt[rg] + 1e-8f);
                float4 s4 = ((const float4*)g_sum)[rg * 32 + c4];
                v.x = s4.x * inv; v.y = s4.y * inv; v.z = s4.z * inv; v.w = s4.w * inv;
            }
        }
        *(float4*)&Xs[r * XSS + c4 * 4] = v;
    }
    // ---- load W1 into shared ----
    #pragma unroll
    for (int s = 0; s < 16; ++s) {
        int e = tid + s * 256;
        ((float4*)Ws)[e] = ((const float4*)W1)[e];
    }
    __syncthreads();

    if (mode == 0) {
        // logmap0 in place: 4 threads per row
        int r = tid >> 2, p = tid & 3;
        float* xr = &Xs[r * XSS + p * 32];
        float ss = 0.f;
        #pragma unroll
        for (int i = 0; i < 32; i++) { float v = xr[i]; ss = fmaf(v, v, ss); }
        ss += __shfl_xor_sync(0xffffffffu, ss, 1);
        ss += __shfl_xor_sync(0xffffffffu, ss, 2);
        float nrm = sqrtf(ss);
        float nc  = fminf(fmaxf(nrm, 1e-8f), 1.0f - 1e-5f);
        float f   = atanhf(nc) / nc;
        #pragma unroll
        for (int i = 0; i < 32; i++) xr[i] *= f;
        __syncthreads();
    }

    float acc[4][8];

    // ---- GEMM1: T = relu(X @ W1 + B1) ----
    {
        float4 b0 = *(const float4*)&B1[tx * 8];
        float4 b1 = *(const float4*)&B1[tx * 8 + 4];
        #pragma unroll
        for (int i = 0; i < 4; i++) {
            acc[i][0] = b0.x; acc[i][1] = b0.y; acc[i][2] = b0.z; acc[i][3] = b0.w;
            acc[i][4] = b1.x; acc[i][5] = b1.y; acc[i][6] = b1.z; acc[i][7] = b1.w;
        }
    }
    #pragma unroll 8
    for (int k = 0; k < D; k++) {
        float a[4];
        #pragma unroll
        for (int i = 0; i < 4; i++) a[i] = Xs[(ty * 4 + i) * XSS + k];
        float4 w0 = *(const float4*)&Ws[k * D + tx * 8];
        float4 w1 = *(const float4*)&Ws[k * D + tx * 8 + 4];
        float w[8] = {w0.x, w0.y, w0.z, w0.w, w1.x, w1.y, w1.z, w1.w};
        #pragma unroll
        for (int i = 0; i < 4; i++)
            #pragma unroll
            for (int j = 0; j < 8; j++)
                acc[i][j] = fmaf(a[i], w[j], acc[i][j]);
    }
    #pragma unroll
    for (int i = 0; i < 4; i++) {
        float* tr = &Ts[(ty * 4 + i) * XSS + tx * 8];
        #pragma unroll
        for (int j = 0; j < 8; j++) tr[j] = fmaxf(acc[i][j], 0.f);
    }
    __syncthreads();          // GEMM1 fully done; safe to overwrite Ws

    // ---- load W2 ----
    #pragma unroll
    for (int s = 0; s < 16; ++s) {
        int e = tid + s * 256;
        ((float4*)Ws)[e] = ((const float4*)W2)[e];
    }
    __syncthreads();

    // ---- GEMM2: V = T @ W2 + B2 ----
    {
        float4 b0 = *(const float4*)&B2[tx * 8];
        float4 b1 = *(const float4*)&B2[tx * 8 + 4];
        #pragma unroll
        for (int i = 0; i < 4; i++) {
            acc[i][0] = b0.x; acc[i][1] = b0.y; acc[i][2] = b0.z; acc[i][3] = b0.w;
            acc[i][4] = b1.x; acc[i][5] = b1.y; acc[i][6] = b1.z; acc[i][7] = b1.w;
        }
    }
    #pragma unroll 8
    for (int k = 0; k < D; k++) {
        float a[4];
        #pragma unroll
        for (int i = 0; i < 4; i++) a[i] = Ts[(ty * 4 + i) * XSS + k];
        float4 w0 = *(const float4*)&Ws[k * D + tx * 8];
        float4 w1 = *(const float4*)&Ws[k * D + tx * 8 + 4];
        float w[8] = {w0.x, w0.y, w0.z, w0.w, w1.x, w1.y, w1.z, w1.w};
        #pragma unroll
        for (int i = 0; i < 4; i++)
            #pragma unroll
            for (int j = 0; j < 8; j++)
                acc[i][j] = fmaf(a[i], w[j], acc[i][j]);
    }

    if (mode == 0) {
        #pragma unroll
        for (int i = 0; i < 4; i++) {
            int rg = row0 + ty * 4 + i;
            if (rg < N) {
                *(float4*)&g_y[rg * D + tx * 8]     = make_float4(acc[i][0], acc[i][1], acc[i][2], acc[i][3]);
                *(float4*)&g_y[rg * D + tx * 8 + 4] = make_float4(acc[i][4], acc[i][5], acc[i][6], acc[i][7]);
            }
        }
    } else {
        __syncthreads();      // GEMM2 reads of Ts done; safe to overwrite
        #pragma unroll
        for (int i = 0; i < 4; i++) {
            float* tr = &Ts[(ty * 4 + i) * XSS + tx * 8];
            #pragma unroll
            for (int j = 0; j < 8; j++) tr[j] = acc[i][j];
        }
        __syncthreads();
        // expmap0: 4 threads per row
        int r = tid >> 2, p = tid & 3;
        float* vr = &Ts[r * XSS + p * 32];
        float ss = 0.f;
        #pragma unroll
        for (int i = 0; i < 32; i++) { float v = vr[i]; ss = fmaf(v, v, ss); }
        ss += __shfl_xor_sync(0xffffffffu, ss, 1);
        ss += __shfl_xor_sync(0xffffffffu, ss, 2);
        float nrm = sqrtf(ss);
        float nc  = fmaxf(nrm, 1e-8f);
        float f   = tanhf(nc) / nc;
        int rg = row0 + r;
        if (rg < N) {
            #pragma unroll
            for (int i = 0; i < 8; i++) {
                float4 o;
                o.x = vr[i * 4 + 0] * f; o.y = vr[i * 4 + 1] * f;
                o.z = vr[i * 4 + 2] * f; o.w = vr[i * 4 + 3] * f;
                *(float4*)&out[rg * D + p * 32 + i * 4] = o;
            }
        }
    }
}

extern "C" void kernel_launch(void* const* d_in, const int* in_sizes, int n_in,
                              void* d_out, int out_size) {
    const float* x      = (const float*)d_in[0];
    const int*   ei     = (const int*)d_in[1];
    const float* w_msg1 = (const float*)d_in[2];
    const float* b_msg1 = (const float*)d_in[3];
    const float* w_msg2 = (const float*)d_in[4];
    const float* b_msg2 = (const float*)d_in[5];
    const float* w_upd1 = (const float*)d_in[6];
    const float* b_upd1 = (const float*)d_in[7];
    const float* w_upd2 = (const float*)d_in[8];
    const float* b_upd2 = (const float*)d_in[9];
    float* out = (float*)d_out;

    int N = in_sizes[0] / D;
    int E = in_sizes[1] / 2;

    size_t smem = (size_t)(2 * TM * XSS + D * D) * sizeof(float);
    cudaFuncSetAttribute(fused_mlp_kernel,
                         cudaFuncAttributeMaxDynamicSharedMemorySize, (int)smem);

    int n4 = N * D / 4;
    int zmax = n4 > N ? n4 : N;
    zero_kernel<<<(zmax + 255) / 256, 256>>>(n4, N);

    int mblocks = (N + TM - 1) / TM;
    // y = MLP1(logmap0(x))  — computed per NODE, not per edge (12x FLOP saving)
    fused_mlp_kernel<<<mblocks, 256, smem>>>(x, w_msg1, b_msg1, w_msg2, b_msg2,
                                             nullptr, N, 0);

    long long sthreads = (long long)E * 32;
    int sblocks = (int)((sthreads + 255) / 256);
    scatter_kernel<<<sblocks, 256>>>(ei, E);

    // out = expmap0(MLP2(sum/cnt))
    fused_mlp_kernel<<<mblocks, 256, smem>>>(nullptr, w_upd1, b_upd1, w_upd2, b_upd2,
                                             out, N, 1);
}

// round 3
// speedup vs baseline: 1.7674x; 1.7674x over previous
#include <cuda_runtime.h>
#include <cuda_bf16.h>
#include <cstdint>

#define D     128
#define NMAX  50000
#define EPS   1e-8f

#define SWB32 68            // A/W smem row stride in b32 units (136 bf16 = 272B)
#define ROWB  272           // bytes per bf16 tile row
#define SWF   132           // f32 staging stride

// ---------------- scratch (static device globals) ----------------
__device__ float g_y[NMAX * D];
__device__ float g_sum[NMAX * D];
__device__ float g_cnt[NMAX];
// transposed + split weights: [mat][n][k] bf16; mat: 0=msg1,1=msg2,2=upd1,3=upd2
__device__ __nv_bfloat16 g_wth[4 * D * D];
__device__ __nv_bfloat16 g_wtl[4 * D * D];

// ---------------- smem layout (bytes) ----------------
#define OFF_AH 0u
#define OFF_AL 34816u
#define OFF_WH 69632u
#define OFF_WL 104448u
#define OFF_B1 139264u
#define OFF_B2 139776u
#define SMEM_DYN 140288u

// ---------------- mma.sync helper (bf16, fp32 accum) ----------------
__device__ __forceinline__ void mma16816(float* c, const uint32_t* a,
                                         uint32_t b0, uint32_t b1) {
    asm volatile(
        "mma.sync.aligned.m16n8k16.row.col.f32.bf16.bf16.f32 "
        "{%0,%1,%2,%3}, {%4,%5,%6,%7}, {%8,%9}, {%0,%1,%2,%3};"
        : "+f"(c[0]), "+f"(c[1]), "+f"(c[2]), "+f"(c[3])
        : "r"(a[0]), "r"(a[1]), "r"(a[2]), "r"(a[3]), "r"(b0), "r"(b1));
}

// 3-term split GEMM: acc += (Ah+Al) @ (Wh+Wl)^T  (dropping Al*Wl)
__device__ __forceinline__ void do_gemm(
    const uint32_t* __restrict__ Ah32, const uint32_t* __restrict__ Al32,
    const uint32_t* __restrict__ Wh32, const uint32_t* __restrict__ Wl32,
    int wm, int wn, int gid, int tig, float acc[2][8][4])
{
    #pragma unroll 2
    for (int ks = 0; ks < 8; ks++) {
        uint32_t ah[2][4], al[2][4];
        #pragma unroll
        for (int ms = 0; ms < 2; ms++) {
            int r = wm * 32 + ms * 16 + gid;
            const uint32_t* p = Ah32 + r * SWB32 + ks * 8 + tig;
            ah[ms][0] = p[0]; ah[ms][1] = p[8 * SWB32];
            ah[ms][2] = p[4]; ah[ms][3] = p[8 * SWB32 + 4];
            const uint32_t* q = Al32 + r * SWB32 + ks * 8 + tig;
            al[ms][0] = q[0]; al[ms][1] = q[8 * SWB32];
            al[ms][2] = q[4]; al[ms][3] = q[8 * SWB32 + 4];
        }
        #pragma unroll
        for (int ns = 0; ns < 8; ns++) {
            int nr = wn * 64 + ns * 8 + gid;
            const uint32_t* bp = Wh32 + nr * SWB32 + ks * 8 + tig;
            uint32_t bh0 = bp[0], bh1 = bp[4];
            const uint32_t* bq = Wl32 + nr * SWB32 + ks * 8 + tig;
            uint32_t bl0 = bq[0], bl1 = bq[4];
            #pragma unroll
            for (int ms = 0; ms < 2; ms++) {
                mma16816(acc[ms][ns], ah[ms], bh0, bh1);
                mma16816(acc[ms][ns], ah[ms], bl0, bl1);
                mma16816(acc[ms][ns], al[ms], bh0, bh1);
            }
        }
    }
}

// ---------------- simple kernels ----------------
__global__ void zero_kernel(int n4, int n) {
    int i = blockIdx.x * blockDim.x + threadIdx.x;
    if (i < n4) ((float4*)g_sum)[i] = make_float4(0.f, 0.f, 0.f, 0.f);
    if (i < n)  g_cnt[i] = 0.f;
}

// transpose + bf16 hi/lo split of the 4 weight matrices
__global__ void prep_w_kernel(const float* __restrict__ w0, const float* __restrict__ w1,
                              const float* __restrict__ w2, const float* __restrict__ w3) {
    int g = blockIdx.x * blockDim.x + threadIdx.x;    // 0..16383
    int mat = g >> 12;
    int rem = g & 4095;
    int k = rem >> 5;
    int n4 = rem & 31;
    const float* W = (mat == 0) ? w0 : (mat == 1) ? w1 : (mat == 2) ? w2 : w3;
    float4 v = ((const float4*)W)[k * 32 + n4];
    float a[4] = {v.x, v.y, v.z, v.w};
    #pragma unroll
    for (int j = 0; j < 4; j++) {
        int n = n4 * 4 + j;
        float f = a[j];
        __nv_bfloat16 hi = __float2bfloat16_rn(f);
        __nv_bfloat16 lo = __float2bfloat16_rn(f - __bfloat162float(hi));
        g_wth[mat * D * D + n * D + k] = hi;
        g_wtl[mat * D * D + n * D + k] = lo;
    }
}

// one warp per edge: gather y[col] (L2-resident), atomicAdd into sum[row]
__global__ void scatter_kernel(const int* __restrict__ ei, int E) {
    int g = blockIdx.x * blockDim.x + threadIdx.x;
    int e = g >> 5;
    if (e >= E) return;
    int lane = g & 31;
    int dst = ei[e];
    int src = ei[E + e];
    float4 v = ((const float4*)g_y)[src * 32 + lane];
    atomicAdd(((float4*)g_sum) + dst * 32 + lane, v);
    if (lane == 0) atomicAdd(&g_cnt[dst], 1.0f);
}

// ---------------- fused MLP via mma.sync (HMMA) ----------------
// mode 0: g_y = MLP1(logmap0(x))
// mode 1: out = expmap0(MLP2(g_sum / (g_cnt+eps)))
__global__ __launch_bounds__(256, 1) void mlp_tc_kernel(
    const float* __restrict__ xin,
    const float* __restrict__ B1v, const float* __restrict__ B2v,
    float* __restrict__ outp, int N, int mode)
{
    extern __shared__ char sb[];
    uint32_t* Ah32 = (uint32_t*)(sb + OFF_AH);
    uint32_t* Al32 = (uint32_t*)(sb + OFF_AL);
    uint32_t* Wh32 = (uint32_t*)(sb + OFF_WH);
    uint32_t* Wl32 = (uint32_t*)(sb + OFF_WL);
    float* B1s = (float*)(sb + OFF_B1);
    float* B2s = (float*)(sb + OFF_B2);

    const int tid  = threadIdx.x;
    const int wid  = tid >> 5;
    const int lane = tid & 31;
    const int gid  = lane >> 2;       // fragment group (row/col within 8)
    const int tig  = lane & 3;        // thread-in-group
    const int wm   = wid & 3;         // M32 block
    const int wn   = wid >> 2;        // N64 block
    const int row0 = blockIdx.x * 128;

    if (tid < 128) B1s[tid] = B1v[tid];
    else           B2s[tid - 128] = B2v[tid - 128];

    // ---- load W1 hi/lo into smem ----
    {
        int m1 = mode * 2;
        const float4* sh = (const float4*)(g_wth + m1 * D * D);
        const float4* sl = (const float4*)(g_wtl + m1 * D * D);
        #pragma unroll
        for (int it = 0; it < 8; it++) {
            int idx = tid + it * 256;       // 2048 float4 per matrix
            int n = idx >> 4, c = idx & 15;
            *(float4*)(sb + OFF_WH + n * ROWB + c * 16) = sh[idx];
            *(float4*)(sb + OFF_WL + n * ROWB + c * 16) = sl[idx];
        }
    }

    // ---- load input rows, logmap0 (mode 0) / mean (mode 1), bf16 hi/lo split ----
    {
        const float4* x4 = (const float4*)xin;
        #pragma unroll 4
        for (int i = 0; i < 16; i++) {
            int r = wid * 16 + i;
            int rg = row0 + r;
            float4 v = make_float4(0.f, 0.f, 0.f, 0.f);
            if (rg < N) {
                if (mode == 0) {
                    v = x4[rg * 32 + lane];
                } else {
                    float inv = 1.0f / (g_cnt[rg] + EPS);
                    float4 s4 = ((const float4*)g_sum)[rg * 32 + lane];
                    v.x = s4.x * inv; v.y = s4.y * inv; v.z = s4.z * inv; v.w = s4.w * inv;
                }
            }
            if (mode == 0) {
                float ss = v.x * v.x + v.y * v.y + v.z * v.z + v.w * v.w;
                #pragma unroll
                for (int m = 16; m >= 1; m >>= 1) ss += __shfl_xor_sync(0xffffffffu, ss, m);
                float nrm = sqrtf(ss);
                float nc  = fminf(fmaxf(nrm, EPS), 1.0f - 1e-5f);
                float f   = atanhf(nc) / nc;
                v.x *= f; v.y *= f; v.z *= f; v.w *= f;
            }
            __nv_bfloat16 h0 = __float2bfloat16_rn(v.x), h1 = __float2bfloat16_rn(v.y);
            __nv_bfloat16 h2 = __float2bfloat16_rn(v.z), h3 = __float2bfloat16_rn(v.w);
            __nv_bfloat162 hp0(h0, h1), hp1(h2, h3);
            __nv_bfloat162 lp0(__float2bfloat16_rn(v.x - __bfloat162float(h0)),
                               __float2bfloat16_rn(v.y - __bfloat162float(h1)));
            __nv_bfloat162 lp1(__float2bfloat16_rn(v.z - __bfloat162float(h2)),
                               __float2bfloat16_rn(v.w - __bfloat162float(h3)));
            *(uint2*)(sb + OFF_AH + r * ROWB + lane * 8) =
                make_uint2(*(uint32_t*)&hp0, *(uint32_t*)&hp1);
            *(uint2*)(sb + OFF_AL + r * ROWB + lane * 8) =
                make_uint2(*(uint32_t*)&lp0, *(uint32_t*)&lp1);
        }
    }
    __syncthreads();

    float acc[2][8][4];

    // ---- GEMM1 ----
    #pragma unroll
    for (int ms = 0; ms < 2; ms++)
        #pragma unroll
        for (int ns = 0; ns < 8; ns++)
            #pragma unroll
            for (int j = 0; j < 4; j++) acc[ms][ns][j] = 0.f;
    do_gemm(Ah32, Al32, Wh32, Wl32, wm, wn, gid, tig, acc);
    __syncthreads();        // all reads of A / W1 complete

    // ---- epilogue1: T = relu(acc + B1) -> Ah/Al (bf16 hi/lo) ----
    #pragma unroll
    for (int ms = 0; ms < 2; ms++) {
        int r = wm * 32 + ms * 16 + gid;
        #pragma unroll
        for (int ns = 0; ns < 8; ns++) {
            int col = wn * 64 + ns * 8 + tig * 2;
            float b0 = B1s[col], b1 = B1s[col + 1];
            float v0 = fmaxf(acc[ms][ns][0] + b0, 0.f);
            float v1 = fmaxf(acc[ms][ns][1] + b1, 0.f);
            float v2 = fmaxf(acc[ms][ns][2] + b0, 0.f);
            float v3 = fmaxf(acc[ms][ns][3] + b1, 0.f);
            __nv_bfloat16 a0 = __float2bfloat16_rn(v0), a1 = __float2bfloat16_rn(v1);
            __nv_bfloat16 a2 = __float2bfloat16_rn(v2), a3 = __float2bfloat16_rn(v3);
            __nv_bfloat162 hA(a0, a1), hB(a2, a3);
            __nv_bfloat162 lA(__float2bfloat16_rn(v0 - __bfloat162float(a0)),
                              __float2bfloat16_rn(v1 - __bfloat162float(a1)));
            __nv_bfloat162 lB(__float2bfloat16_rn(v2 - __bfloat162float(a2)),
                              __float2bfloat16_rn(v3 - __bfloat162float(a3)));
            *(uint32_t*)(sb + OFF_AH + r * ROWB + col * 2)           = *(uint32_t*)&hA;
            *(uint32_t*)(sb + OFF_AL + r * ROWB + col * 2)           = *(uint32_t*)&lA;
            *(uint32_t*)(sb + OFF_AH + (r + 8) * ROWB + col * 2)     = *(uint32_t*)&hB;
            *(uint32_t*)(sb + OFF_AL + (r + 8) * ROWB + col * 2)     = *(uint32_t*)&lB;
        }
    }

    // ---- load W2 hi/lo ----
    {
        int m2 = mode * 2 + 1;
        const float4* sh = (const float4*)(g_wth + m2 * D * D);
        const float4* sl = (const float4*)(g_wtl + m2 * D * D);
        #pragma unroll
        for (int it = 0; it < 8; it++) {
            int idx = tid + it * 256;
            int n = idx >> 4, c = idx & 15;
            *(float4*)(sb + OFF_WH + n * ROWB + c * 16) = sh[idx];
            *(float4*)(sb + OFF_WL + n * ROWB + c * 16) = sl[idx];
        }
    }
    __syncthreads();

    // ---- GEMM2 ----
    #pragma unroll
    for (int ms = 0; ms < 2; ms++)
        #pragma unroll
        for (int ns = 0; ns < 8; ns++)
            #pragma unroll
            for (int j = 0; j < 4; j++) acc[ms][ns][j] = 0.f;
    do_gemm(Ah32, Al32, Wh32, Wl32, wm, wn, gid, tig, acc);

    if (mode == 0) {
        // direct store: g_y = acc + B2
        #pragma unroll
        for (int ms = 0; ms < 2; ms++) {
            int r = wm * 32 + ms * 16 + gid;
            #pragma unroll
            for (int ns = 0; ns < 8; ns++) {
                int col = wn * 64 + ns * 8 + tig * 2;
                float b0 = B2s[col], b1 = B2s[col + 1];
                int rg = row0 + r;
                if (rg < N)
                    *(float2*)(g_y + rg * D + col) =
                        make_float2(acc[ms][ns][0] + b0, acc[ms][ns][1] + b1);
                if (rg + 8 < N)
                    *(float2*)(g_y + (rg + 8) * D + col) =
                        make_float2(acc[ms][ns][2] + b0, acc[ms][ns][3] + b1);
            }
        }
    } else {
        __syncthreads();    // W2 reads done; reuse WH/WL region as f32 staging
        float* Sf = (float*)(sb + OFF_WH);
        #pragma unroll
        for (int ms = 0; ms < 2; ms++) {
            int r = wm * 32 + ms * 16 + gid;
            #pragma unroll
            for (int ns = 0; ns < 8; ns++) {
                int col = wn * 64 + ns * 8 + tig * 2;
                float b0 = B2s[col], b1 = B2s[col + 1];
                *(float2*)(Sf + r * SWF + col) =
                    make_float2(acc[ms][ns][0] + b0, acc[ms][ns][1] + b1);
                *(float2*)(Sf + (r + 8) * SWF + col) =
                    make_float2(acc[ms][ns][2] + b0, acc[ms][ns][3] + b1);
            }
        }
        __syncthreads();
        // expmap0: 2 threads per row
        int r = tid >> 1, h = tid & 1;
        float ss = 0.f;
        float4 vv[16];
        #pragma unroll
        for (int j = 0; j < 16; j++) {
            float4 v = *(float4*)(Sf + r * SWF + h * 64 + j * 4);
            vv[j] = v;
            ss += v.x * v.x + v.y * v.y + v.z * v.z + v.w * v.w;
        }
        ss += __shfl_xor_sync(0xffffffffu, ss, 1);
        float nrm = sqrtf(ss);
        float nc  = fmaxf(nrm, EPS);
        float fm  = tanhf(nc) / nc;
        int rg = row0 + r;
        if (rg < N) {
            #pragma unroll
            for (int j = 0; j < 16; j++) {
                float4 v = vv[j];
                v.x *= fm; v.y *= fm; v.z *= fm; v.w *= fm;
                ((float4*)outp)[rg * 32 + h * 16 + j] = v;
            }
        }
    }
}

// ---------------- launch ----------------
extern "C" void kernel_launch(void* const* d_in, const int* in_sizes, int n_in,
                              void* d_out, int out_size) {
    const float* x      = (const float*)d_in[0];
    const int*   ei     = (const int*)d_in[1];
    const float* w_msg1 = (const float*)d_in[2];
    const float* b_msg1 = (const float*)d_in[3];
    const float* w_msg2 = (const float*)d_in[4];
    const float* b_msg2 = (const float*)d_in[5];
    const float* w_upd1 = (const float*)d_in[6];
    const float* b_upd1 = (const float*)d_in[7];
    const float* w_upd2 = (const float*)d_in[8];
    const float* b_upd2 = (const float*)d_in[9];
    float* out = (float*)d_out;

    int N = in_sizes[0] / D;
    int E = in_sizes[1] / 2;

    cudaFuncSetAttribute(mlp_tc_kernel,
                         cudaFuncAttributeMaxDynamicSharedMemorySize, SMEM_DYN);

    prep_w_kernel<<<64, 256>>>(w_msg1, w_msg2, w_upd1, w_upd2);

    int n4 = N * D / 4;
    int zmax = n4 > N ? n4 : N;
    zero_kernel<<<(zmax + 255) / 256, 256>>>(n4, N);

    int mblocks = (N + 127) / 128;
    mlp_tc_kernel<<<mblocks, 256, SMEM_DYN>>>(x, b_msg1, b_msg2, nullptr, N, 0);

    long long sthreads = (long long)E * 32;
    int sblocks = (int)((sthreads + 255) / 256);
    scatter_kernel<<<sblocks, 256>>>(ei, E);

    mlp_tc_kernel<<<mblocks, 256, SMEM_DYN>>>(nullptr, b_upd1, b_upd2, out, N, 1);
}